// round 16
// baseline (speedup 1.0000x reference)
#include <cuda_runtime.h>
#include <cuda_fp16.h>
#include <math.h>
#include <stdint.h>

// Problem constants
#define Bb  2
#define Ss  2048
#define Dd  1024
#define Hh  16
#define HDd 64
#define Tt  (Bb*Ss)   // 4096 tokens
#define E3  (3*Dd)    // 3072

// Scratch (device globals — no allocations allowed)
__device__ __half g_qh[(size_t)Bb*Hh*Ss*HDd];   // [b][h][s][hd], pre-scaled x(0.125*log2e)
__device__ __half g_kh[(size_t)Bb*Hh*Ss*HDd];
__device__ __half g_vh[(size_t)Bb*Hh*Ss*HDd];
__device__ __half g_oh[(size_t)Tt*Dd];          // [t][d]
__device__ float  g_cos[Ss*32];
__device__ float  g_sin[Ss*32];
__device__ __half g_xh [(size_t)Tt*Dd];         // fp16 X
__device__ __half g_wqh[(size_t)E3*Dd];         // fp16 w_qkv
__device__ __half g_woh[(size_t)Dd*Dd];         // fp16 w_out

#define QSCALE (0.125f * 1.4426950408889634f)   // fold log2e: softmax in exp2 domain
#define MSHIFT 5.0f                              // fixed softmax shift (log2 domain)

// ---------------------------------------------------------------------------
// helpers
// ---------------------------------------------------------------------------
__device__ __forceinline__ uint32_t pack_half2(float a, float b) {
    __half2 h = __floats2half2_rn(a, b);
    return *reinterpret_cast<uint32_t*>(&h);
}

__device__ __forceinline__ float ex2f(float x) {
    float y;
    asm("ex2.approx.ftz.f32 %0, %1;" : "=f"(y) : "f"(x));
    return y;
}

__device__ __forceinline__ void mma_f16(float c[4],
                                        const uint32_t a[4],
                                        const uint32_t b[2]) {
    asm volatile(
        "mma.sync.aligned.m16n8k16.row.col.f32.f16.f16.f32 "
        "{%0,%1,%2,%3},{%4,%5,%6,%7},{%8,%9},{%0,%1,%2,%3};\n"
        : "+f"(c[0]), "+f"(c[1]), "+f"(c[2]), "+f"(c[3])
        : "r"(a[0]), "r"(a[1]), "r"(a[2]), "r"(a[3]),
          "r"(b[0]), "r"(b[1]));
}

__device__ __forceinline__ void ldmx4(uint32_t& r0, uint32_t& r1,
                                      uint32_t& r2, uint32_t& r3, uint32_t addr) {
    asm volatile("ldmatrix.sync.aligned.m8n8.x4.shared.b16 {%0,%1,%2,%3}, [%4];"
                 : "=r"(r0), "=r"(r1), "=r"(r2), "=r"(r3) : "r"(addr));
}
__device__ __forceinline__ void ldmx4t(uint32_t& r0, uint32_t& r1,
                                       uint32_t& r2, uint32_t& r3, uint32_t addr) {
    asm volatile("ldmatrix.sync.aligned.m8n8.x4.trans.shared.b16 {%0,%1,%2,%3}, [%4];"
                 : "=r"(r0), "=r"(r1), "=r"(r2), "=r"(r3) : "r"(addr));
}

__device__ __forceinline__ void cp_async16(const void* smem_dst,
                                           const void* gmem_src) {
    uint32_t sa = (uint32_t)__cvta_generic_to_shared(smem_dst);
    asm volatile("cp.async.cg.shared.global [%0], [%1], 16;\n"
                 :: "r"(sa), "l"(gmem_src));
}
__device__ __forceinline__ void cp_commit() {
    asm volatile("cp.async.commit_group;\n");
}
template<int N>
__device__ __forceinline__ void cp_wait() {
    asm volatile("cp.async.wait_group %0;\n" :: "n"(N));
}

// ---------------------------------------------------------------------------
// Kernel 0: fused input conversion (fp32->fp16) + RoPE cos/sin table.
// ---------------------------------------------------------------------------
#define N_X  (Tt * Dd)
#define N_WQ (E3 * Dd)
#define N_WO (Dd * Dd)
#define NB_CONV ((N_X + N_WQ + N_WO) / 8 / 256)   // 4096

__global__ void prep_kernel(const float* __restrict__ x,
                            const float* __restrict__ wq,
                            const float* __restrict__ wo) {
    int bid = blockIdx.x;
    if (bid < NB_CONV) {
        int i = (bid * 256 + threadIdx.x) * 8;
        const float* src;
        __half* dst;
        if (i < N_X)             { src = x  + i;          dst = g_xh  + i; }
        else if (i < N_X + N_WQ) { src = wq + (i - N_X);  dst = g_wqh + (i - N_X); }
        else {
            src = wo + (i - N_X - N_WQ);
            dst = g_woh + (i - N_X - N_WQ);
        }
        float4 a = *(const float4*)(src);
        float4 b = *(const float4*)(src + 4);
        uint4 o;
        o.x = pack_half2(a.x, a.y);
        o.y = pack_half2(a.z, a.w);
        o.z = pack_half2(b.x, b.y);
        o.w = pack_half2(b.z, b.w);
        *(uint4*)(dst) = o;
    } else {
        int idx = (bid - NB_CONV) * 256 + threadIdx.x;   // 0..65535
        int s = idx >> 5;
        int j = idx & 31;
        double theta = exp(-((double)j / 32.0) * log(10000.0));
        double a = (double)s * theta;
        g_cos[idx] = (float)cos(a);
        g_sin[idx] = (float)sin(a);
    }
}

// ---------------------------------------------------------------------------
// GEMM core (fp16, m16n8k16, warp tile 64x64, CTA tile 128x128, 128 threads):
// 3-stage cp.async ring, K-chunk 64, 1 sync per chunk. 2 CTAs/SM.
// ---------------------------------------------------------------------------
#define HST 72
#define BM 128
#define BN 128
#define NROWS (BM + BN)                 // 256
#define GSTAGE (NROWS * HST)            // halves per stage
#define GEMM_SMEM (3 * GSTAGE * 2)      // 110592 B

__device__ __forceinline__ void gemm_core_f16(
    const __half* __restrict__ A, const __half* __restrict__ B,
    int m0, int n0, int K,
    __half* __restrict__ smemh,
    float acc[4][8][4])
{
    const int tid  = threadIdx.x;
    const int warp = tid >> 5;     // 0..3
    const int lane = tid & 31;
    const int wm   = warp >> 1;    // 0..1
    const int wn   = warp & 1;     // 0..1

    const int lr = lane & 7;
    const int ra = lr + ((lane >> 3) & 1) * 8;
    const int ca = (lane >> 4) * 8;
    const int rb = lr + (lane >> 4) * 8;
    const int cb = ((lane >> 3) & 1) * 8;

    const uint32_t smem_u = (uint32_t)__cvta_generic_to_shared(smemh);
    const int n_iters = K >> 6;

    auto issue = [&](int it) {
        int k0 = it << 6;
        __half* st = smemh + (it % 3) * GSTAGE;
        #pragma unroll
        for (int j = 0; j < 16; j++) {
            int idx = j * 128 + tid;
            int row = idx >> 3;
            int seg = (idx & 7) * 8;
            const __half* src = (row < BM)
                ? A + (size_t)(m0 + row) * K + k0 + seg
                : B + (size_t)(n0 + row - BM) * K + k0 + seg;
            cp_async16(st + row * HST + seg, src);
        }
    };

    issue(0); cp_commit();
    issue(1); cp_commit();

    for (int i = 0; i < n_iters; i++) {
        cp_wait<1>();
        __syncthreads();
        if (i + 2 < n_iters) issue(i + 2);
        cp_commit();

        const uint32_t base = smem_u + (uint32_t)((i % 3) * GSTAGE * 2);

        #pragma unroll
        for (int ka = 0; ka < 4; ka++) {
            const int kb = ka * 16;
            uint32_t af[4][4], bf[8][2];
            #pragma unroll
            for (int ma = 0; ma < 4; ma++)
                ldmx4(af[ma][0], af[ma][1], af[ma][2], af[ma][3],
                      base + 2u * (uint32_t)((wm * 64 + ma * 16 + ra) * HST + kb + ca));
            #pragma unroll
            for (int np = 0; np < 4; np++)
                ldmx4(bf[2*np][0], bf[2*np][1], bf[2*np+1][0], bf[2*np+1][1],
                      base + 2u * (uint32_t)((BM + wn * 64 + np * 16 + rb) * HST + kb + cb));
            #pragma unroll
            for (int ma = 0; ma < 4; ma++)
                #pragma unroll
                for (int na = 0; na < 8; na++)
                    mma_f16(acc[ma][na], af[ma], bf[na]);
        }
    }
    cp_wait<0>();
    __syncthreads();
}

// ---------------------------------------------------------------------------
// Kernel 1: QKV GEMM + register RoPE + fp16 scatter. grid = (24, 32).
// ---------------------------------------------------------------------------
__global__ __launch_bounds__(128)
void qkv_rope_kernel() {
    extern __shared__ char dsm_c[];
    __half* smh = (__half*)dsm_c;

    const int tid = threadIdx.x;
    const int m0 = blockIdx.y * BM;
    const int n0 = blockIdx.x * BN;
    const int warp = tid >> 5;
    const int lane = tid & 31;
    const int wm = warp >> 1, wn = warp & 1;
    const int grp = lane >> 2, tg = lane & 3;

    float acc[4][8][4];
    #pragma unroll
    for (int i = 0; i < 4; i++)
        #pragma unroll
        for (int j = 0; j < 8; j++)
            #pragma unroll
            for (int v = 0; v < 4; v++) acc[i][j][v] = 0.0f;

    gemm_core_f16(g_xh, g_wqh, m0, n0, 1024, smh, acc);

    const int basehead = (n0 >> 6) + wn;      // 0..47, uniform per warp

    if (basehead < 32) {
        float* sCos = (float*)dsm_c;
        float* sSin = sCos + BM * 32;
        for (int i = tid; i < BM * 32; i += 128) {
            int r = i >> 5, c = i & 31;
            int s = (m0 + r) & 2047;
            sCos[i] = g_cos[(s << 5) + c];
            sSin[i] = g_sin[(s << 5) + c];
        }
        __syncthreads();

        const float qs = (basehead < 16) ? QSCALE : 1.0f;
        #pragma unroll
        for (int ma = 0; ma < 4; ma++) {
            #pragma unroll
            for (int hf = 0; hf < 2; hf++) {
                int r = wm * 64 + ma * 16 + grp + hf * 8;
                int t = m0 + r;
                int b = t >> 11, s = t & 2047;
                __half* dst = (basehead < 16)
                    ? g_qh + (((size_t)(b * Hh + basehead)      << 11) + s) * 64
                    : g_kh + (((size_t)(b * Hh + basehead - 16) << 11) + s) * 64;
                #pragma unroll
                for (int na = 0; na < 8; na++) {
                    int c0 = na * 8 + 2 * tg;
                    float v0 = acc[ma][na][hf*2 + 0];
                    float v1 = acc[ma][na][hf*2 + 1];
                    float p0 = acc[ma][na ^ 4][hf*2 + 0];
                    float p1 = acc[ma][na ^ 4][hf*2 + 1];
                    float sg = (na < 4) ? -1.0f : 1.0f;
                    float cs0 = sCos[(r << 5) + (c0 & 31)];
                    float sn0 = sSin[(r << 5) + (c0 & 31)];
                    float cs1 = sCos[(r << 5) + ((c0 + 1) & 31)];
                    float sn1 = sSin[(r << 5) + ((c0 + 1) & 31)];
                    float o0 = (v0 * cs0 + sg * p0 * sn0) * qs;
                    float o1 = (v1 * cs1 + sg * p1 * sn1) * qs;
                    *(uint32_t*)(dst + c0) = pack_half2(o0, o1);
                }
            }
        }
    } else {
        #pragma unroll
        for (int ma = 0; ma < 4; ma++) {
            #pragma unroll
            for (int hf = 0; hf < 2; hf++) {
                int r = wm * 64 + ma * 16 + grp + hf * 8;
                int t = m0 + r;
                int b = t >> 11, s = t & 2047;
                __half* dst = g_vh +
                    (((size_t)(b * Hh + basehead - 32) << 11) + s) * 64;
                #pragma unroll
                for (int na = 0; na < 8; na++) {
                    int c0 = na * 8 + 2 * tg;
                    *(uint32_t*)(dst + c0) =
                        pack_half2(acc[ma][na][hf*2], acc[ma][na][hf*2 + 1]);
                }
            }
        }
    }
}

// ---------------------------------------------------------------------------
// Kernel 3: output projection + bias (128x128 tile). grid = (8, 32), 1 wave.
// ---------------------------------------------------------------------------
__global__ __launch_bounds__(128)
void proj_kernel(const float* __restrict__ bias, float* __restrict__ out) {
    extern __shared__ char dsm_c[];
    __half* smh = (__half*)dsm_c;

    const int tid = threadIdx.x;
    const int m0 = blockIdx.y * BM;
    const int n0 = blockIdx.x * BN;
    const int warp = tid >> 5;
    const int lane = tid & 31;
    const int wm = warp >> 1, wn = warp & 1;
    const int grp = lane >> 2, tg = lane & 3;

    float acc[4][8][4];
    #pragma unroll
    for (int i = 0; i < 4; i++)
        #pragma unroll
        for (int j = 0; j < 8; j++)
            #pragma unroll
            for (int v = 0; v < 4; v++) acc[i][j][v] = 0.0f;

    gemm_core_f16(g_oh, g_woh, m0, n0, 1024, smh, acc);

    #pragma unroll
    for (int ma = 0; ma < 4; ma++) {
        int r0 = m0 + wm * 64 + ma * 16 + grp;
        #pragma unroll
        for (int na = 0; na < 8; na++) {
            int col = n0 + wn * 64 + na * 8 + 2 * tg;
            float b0 = bias[col], b1 = bias[col + 1];
            *(float2*)(out + (size_t)r0 * 1024 + col) =
                make_float2(acc[ma][na][0] + b0, acc[ma][na][1] + b1);
            *(float2*)(out + (size_t)(r0 + 8) * 1024 + col) =
                make_float2(acc[ma][na][2] + b0, acc[ma][na][3] + b1);
        }
    }
}

// ---------------------------------------------------------------------------
// Kernel 2: causal flash attention. l accumulated on the (idle) fma pipe
// with fp32 FADDs; ones-column mma removed from the saturated tensor pipe.
// fp16 mma, register P, fixed-shift exp2 softmax, 3-stage cp.async ring, LPT.
// ---------------------------------------------------------------------------
#define ATTN_SMEM ((128 * HST + 6 * 64 * HST) * 2)   // 73728 B

__global__ __launch_bounds__(256)
void attn_kernel() {
    extern __shared__ char asc[];
    __half* sQ  = (__half*)asc;
    __half* sKs = sQ + 128 * HST;
    __half* sVs = sKs + 3 * 64 * HST;

    const int tid  = threadIdx.x;
    const int warp = tid >> 5;
    const int lane = tid & 31;
    const int grp  = lane >> 2;
    const int tg   = lane & 3;

    const int lr8 = lane & 7;
    const int ra = lr8 + ((lane >> 3) & 1) * 8;
    const int ca = (lane >> 4) * 8;
    const int rb = lr8 + (lane >> 4) * 8;
    const int cb = ((lane >> 3) & 1) * 8;

    const int bh = blockIdx.x;                            // fast axis: heads
    const int q0 = (gridDim.y - 1 - blockIdx.y) * 128;    // heavy q first
    const int b  = bh >> 4;
    const int h  = bh & 15;

    const __half* Qg = g_qh + ((size_t)bh * Ss + q0) * 64;
    const __half* Kg = g_kh + (size_t)bh * Ss * 64;
    const __half* Vg = g_vh + (size_t)bh * Ss * 64;

    const uint32_t sQ_u  = (uint32_t)__cvta_generic_to_shared(sQ);
    const uint32_t sKs_u = (uint32_t)__cvta_generic_to_shared(sKs);
    const uint32_t sVs_u = (uint32_t)__cvta_generic_to_shared(sVs);

    const int n_tiles = (q0 >> 6) + 2;

    auto kv_issue = [&](int tile) {
        int kv = tile << 6;
        int st = tile % 3;
        __half* dK = sKs + st * 64 * HST;
        __half* dV = sVs + st * 64 * HST;
        const int r = tid >> 2;
        const int s2 = (tid & 3) * 16;
        #pragma unroll
        for (int i = 0; i < 2; i++) {
            cp_async16(dK + r * HST + s2 + i * 8,
                       Kg + (size_t)(kv + r) * 64 + s2 + i * 8);
            cp_async16(dV + r * HST + s2 + i * 8,
                       Vg + (size_t)(kv + r) * 64 + s2 + i * 8);
        }
    };

    {
        const int r = tid >> 1;
        const int s4 = (tid & 1) * 32;
        #pragma unroll
        for (int i = 0; i < 4; i++)
            cp_async16(sQ + r * HST + s4 + i * 8,
                       Qg + (size_t)r * 64 + s4 + i * 8);
    }
    cp_commit();
    kv_issue(0); cp_commit();
    kv_issue(1); cp_commit();

    cp_wait<2>();
    __syncthreads();

    uint32_t qa[4][4];
    #pragma unroll
    for (int ka = 0; ka < 4; ka++)
        ldmx4(qa[ka][0], qa[ka][1], qa[ka][2], qa[ka][3],
              sQ_u + 2u * (uint32_t)((warp * 16 + ra) * HST + ka * 16 + ca));

    float oacc[8][4];
    #pragma unroll
    for (int na = 0; na < 8; na++)
        #pragma unroll
        for (int v = 0; v < 4; v++) oacc[na][v] = 0.0f;
    float l0r = 0.0f, l1r = 0.0f;   // fp32 row-sum partials (fma pipe)

    const int row0g = q0 + warp * 16 + grp;
    const int row1g = row0g + 8;

    for (int ti = 0; ti < n_tiles; ti++) {
        cp_wait<1>();
        __syncthreads();
        if (ti + 2 < n_tiles) kv_issue(ti + 2);
        cp_commit();

        const int st = ti % 3;
        const uint32_t cK_u = sKs_u + (uint32_t)(st * 64 * HST * 2);
        const uint32_t cV_u = sVs_u + (uint32_t)(st * 64 * HST * 2);
        const int kv0 = ti << 6;

        float sacc[8][4];
        #pragma unroll
        for (int na = 0; na < 8; na++)
            #pragma unroll
            for (int v = 0; v < 4; v++) sacc[na][v] = -MSHIFT;

        #pragma unroll
        for (int ka = 0; ka < 4; ka++) {
            const int kb = ka * 16;
            uint32_t bf[8][2];
            #pragma unroll
            for (int np = 0; np < 4; np++)
                ldmx4(bf[2*np][0], bf[2*np][1], bf[2*np+1][0], bf[2*np+1][1],
                      cK_u + 2u * (uint32_t)((np * 16 + rb) * HST + kb + cb));
            #pragma unroll
            for (int na = 0; na < 8; na++)
                mma_f16(sacc[na], qa[ka], bf[na]);
        }

        if (kv0 + 64 > q0) {
            #pragma unroll
            for (int na = 0; na < 8; na++) {
                int c0 = kv0 + na * 8 + 2 * tg;
                if (c0     > row0g) sacc[na][0] = -1e30f;
                if (c0 + 1 > row0g) sacc[na][1] = -1e30f;
                if (c0     > row1g) sacc[na][2] = -1e30f;
                if (c0 + 1 > row1g) sacc[na][3] = -1e30f;
            }
        }

        // p = 2^(s-MSHIFT); l accumulated in fp32 on the idle fma pipe
        uint32_t pf[8][2];
        #pragma unroll
        for (int na = 0; na < 8; na++) {
            float p0 = ex2f(sacc[na][0]);
            float p1 = ex2f(sacc[na][1]);
            float p2 = ex2f(sacc[na][2]);
            float p3 = ex2f(sacc[na][3]);
            l0r += p0 + p1;
            l1r += p2 + p3;
            pf[na][0] = pack_half2(p0, p1);
            pf[na][1] = pack_half2(p2, p3);
        }

        #pragma unroll
        for (int ka2 = 0; ka2 < 4; ka2++) {
            uint32_t pa[4] = { pf[2*ka2][0],   pf[2*ka2][1],
                               pf[2*ka2+1][0], pf[2*ka2+1][1] };
            #pragma unroll
            for (int np = 0; np < 4; np++) {
                uint32_t b0, b1, b2, b3;
                ldmx4t(b0, b1, b2, b3,
                       cV_u + 2u * (uint32_t)((ka2 * 16 + ra) * HST + np * 16 + ca));
                uint32_t bf0[2] = {b0, b1};
                uint32_t bf1[2] = {b2, b3};
                mma_f16(oacc[2*np],     pa, bf0);
                mma_f16(oacc[2*np + 1], pa, bf1);
            }
        }
    }

    // end-of-kernel row-sum reduce (2 shfl per row) + normalize + write
    l0r += __shfl_xor_sync(0xffffffffu, l0r, 1);
    l0r += __shfl_xor_sync(0xffffffffu, l0r, 2);
    l1r += __shfl_xor_sync(0xffffffffu, l1r, 1);
    l1r += __shfl_xor_sync(0xffffffffu, l1r, 2);
    {
        float inv0 = 1.0f / l0r;
        float inv1 = 1.0f / l1r;
        __half* O0 = g_oh + ((size_t)(b * Ss) + row0g) * 1024 + h * 64;
        __half* O1 = g_oh + ((size_t)(b * Ss) + row1g) * 1024 + h * 64;
        #pragma unroll
        for (int na = 0; na < 8; na++) {
            int c0 = na * 8 + 2 * tg;
            *(uint32_t*)(O0 + c0) = pack_half2(oacc[na][0] * inv0,
                                               oacc[na][1] * inv0);
            *(uint32_t*)(O1 + c0) = pack_half2(oacc[na][2] * inv1,
                                               oacc[na][3] * inv1);
        }
    }
}

// ---------------------------------------------------------------------------
extern "C" void kernel_launch(void* const* d_in, const int* in_sizes, int n_in,
                              void* d_out, int out_size) {
    const float* x     = (const float*)d_in[0];
    const float* w_qkv = (const float*)d_in[1];
    const float* w_out = (const float*)d_in[2];
    const float* b_out = (const float*)d_in[3];
    float* out = (float*)d_out;

    prep_kernel<<<NB_CONV + 256, 256>>>(x, w_qkv, w_out);

    cudaFuncSetAttribute(qkv_rope_kernel,
                         cudaFuncAttributeMaxDynamicSharedMemorySize, GEMM_SMEM);
    cudaFuncSetAttribute(proj_kernel,
                         cudaFuncAttributeMaxDynamicSharedMemorySize, GEMM_SMEM);
    cudaFuncSetAttribute(attn_kernel,
                         cudaFuncAttributeMaxDynamicSharedMemorySize, ATTN_SMEM);

    qkv_rope_kernel<<<dim3(E3 / BN, Tt / BM), 128, GEMM_SMEM>>>();

    attn_kernel<<<dim3(Bb * Hh, Ss / 128), 256, ATTN_SMEM>>>();

    proj_kernel<<<dim3(Dd / BN, Tt / BM), 128, GEMM_SMEM>>>(b_out, out);
}

// round 17
// speedup vs baseline: 1.6015x; 1.6015x over previous
#include <cuda_runtime.h>
#include <cuda_fp16.h>
#include <math.h>
#include <stdint.h>

// Problem constants
#define Bb  2
#define Ss  2048
#define Dd  1024
#define Hh  16
#define HDd 64
#define Tt  (Bb*Ss)   // 4096 tokens
#define E3  (3*Dd)    // 3072

// Scratch (device globals — no allocations allowed)
__device__ __half g_qh[(size_t)Bb*Hh*Ss*HDd];   // [b][h][s][hd], pre-scaled x(0.125*log2e)
__device__ __half g_kh[(size_t)Bb*Hh*Ss*HDd];
__device__ __half g_vh[(size_t)Bb*Hh*Ss*HDd];
__device__ __half g_oh[(size_t)Tt*Dd];          // [t][d]
__device__ float  g_cos[Ss*32];
__device__ float  g_sin[Ss*32];
__device__ __half g_xh [(size_t)Tt*Dd];         // fp16 X
__device__ __half g_wqh[(size_t)E3*Dd];         // fp16 w_qkv
__device__ __half g_woh[(size_t)Dd*Dd];         // fp16 w_out

#define QSCALE (0.125f * 1.4426950408889634f)   // fold log2e: softmax in exp2 domain
#define MSHIFT 5.0f                              // fixed softmax shift (log2 domain)

// ---------------------------------------------------------------------------
// helpers
// ---------------------------------------------------------------------------
__device__ __forceinline__ uint32_t pack_half2(float a, float b) {
    __half2 h = __floats2half2_rn(a, b);
    return *reinterpret_cast<uint32_t*>(&h);
}

__device__ __forceinline__ float ex2f(float x) {
    float y;
    asm("ex2.approx.ftz.f32 %0, %1;" : "=f"(y) : "f"(x));
    return y;
}

__device__ __forceinline__ void mma_f16(float c[4],
                                        const uint32_t a[4],
                                        const uint32_t b[2]) {
    asm volatile(
        "mma.sync.aligned.m16n8k16.row.col.f32.f16.f16.f32 "
        "{%0,%1,%2,%3},{%4,%5,%6,%7},{%8,%9},{%0,%1,%2,%3};\n"
        : "+f"(c[0]), "+f"(c[1]), "+f"(c[2]), "+f"(c[3])
        : "r"(a[0]), "r"(a[1]), "r"(a[2]), "r"(a[3]),
          "r"(b[0]), "r"(b[1]));
}

__device__ __forceinline__ void ldmx4(uint32_t& r0, uint32_t& r1,
                                      uint32_t& r2, uint32_t& r3, uint32_t addr) {
    asm volatile("ldmatrix.sync.aligned.m8n8.x4.shared.b16 {%0,%1,%2,%3}, [%4];"
                 : "=r"(r0), "=r"(r1), "=r"(r2), "=r"(r3) : "r"(addr));
}
__device__ __forceinline__ void ldmx4t(uint32_t& r0, uint32_t& r1,
                                       uint32_t& r2, uint32_t& r3, uint32_t addr) {
    asm volatile("ldmatrix.sync.aligned.m8n8.x4.trans.shared.b16 {%0,%1,%2,%3}, [%4];"
                 : "=r"(r0), "=r"(r1), "=r"(r2), "=r"(r3) : "r"(addr));
}
__device__ __forceinline__ void ldmx2t(uint32_t& r0, uint32_t& r1, uint32_t addr) {
    asm volatile("ldmatrix.sync.aligned.m8n8.x2.trans.shared.b16 {%0,%1}, [%2];"
                 : "=r"(r0), "=r"(r1) : "r"(addr));
}

__device__ __forceinline__ void cp_async16(const void* smem_dst,
                                           const void* gmem_src) {
    uint32_t sa = (uint32_t)__cvta_generic_to_shared(smem_dst);
    asm volatile("cp.async.cg.shared.global [%0], [%1], 16;\n"
                 :: "r"(sa), "l"(gmem_src));
}
__device__ __forceinline__ void cp_commit() {
    asm volatile("cp.async.commit_group;\n");
}
template<int N>
__device__ __forceinline__ void cp_wait() {
    asm volatile("cp.async.wait_group %0;\n" :: "n"(N));
}

// ---------------------------------------------------------------------------
// Kernel 0a: RoPE cos/sin table
// ---------------------------------------------------------------------------
__global__ void rope_table_kernel() {
    int idx = blockIdx.x * blockDim.x + threadIdx.x;
    if (idx >= Ss * 32) return;
    int s = idx >> 5;
    int j = idx & 31;
    double theta = exp(-((double)j / 32.0) * log(10000.0));
    double a = (double)s * theta;
    g_cos[idx] = (float)cos(a);
    g_sin[idx] = (float)sin(a);
}

// ---------------------------------------------------------------------------
// Kernel 0b: fused fp32 -> fp16 conversion of all three inputs
// ---------------------------------------------------------------------------
#define N_X  (Tt * Dd)
#define N_WQ (E3 * Dd)
#define N_WO (Dd * Dd)

__global__ void f2h_all_kernel(const float* __restrict__ x,
                               const float* __restrict__ wq,
                               const float* __restrict__ wo) {
    int i = (blockIdx.x * blockDim.x + threadIdx.x) * 8;
    const float* src;
    __half* dst;
    if (i < N_X)               { src = x  + i;               dst = g_xh  + i; }
    else if (i < N_X + N_WQ)   { src = wq + (i - N_X);       dst = g_wqh + (i - N_X); }
    else if (i < N_X + N_WQ + N_WO) {
        src = wo + (i - N_X - N_WQ);
        dst = g_woh + (i - N_X - N_WQ);
    } else return;
    float4 a = *(const float4*)(src);
    float4 b = *(const float4*)(src + 4);
    uint4 o;
    o.x = pack_half2(a.x, a.y);
    o.y = pack_half2(a.z, a.w);
    o.z = pack_half2(b.x, b.y);
    o.w = pack_half2(b.z, b.w);
    *(uint4*)(dst) = o;
}

// ---------------------------------------------------------------------------
// GEMM core v3 (fp16, m16n8k16, warp tile 64x64, CTA tile 128x128,
// 128 threads / 4 warps): 2 CTAs/SM. 3-stage cp.async ring, K-chunk 64,
// 1 sync per chunk. smem: 3 stages x 256 rows x 144B = 110592 B per CTA.
// ---------------------------------------------------------------------------
#define HST 72
#define BM 128
#define BN 128
#define NROWS (BM + BN)                 // 256
#define GSTAGE (NROWS * HST)            // halves per stage
#define GEMM_SMEM (3 * GSTAGE * 2)      // 110592 B

__device__ __forceinline__ void gemm_core_f16(
    const __half* __restrict__ A, const __half* __restrict__ B,
    int m0, int n0, int K,
    __half* __restrict__ smemh,
    float acc[4][8][4])
{
    const int tid  = threadIdx.x;
    const int warp = tid >> 5;     // 0..3
    const int lane = tid & 31;
    const int wm   = warp >> 1;    // 0..1
    const int wn   = warp & 1;     // 0..1

    const int lr = lane & 7;
    const int ra = lr + ((lane >> 3) & 1) * 8;   // A-fragment rows
    const int ca = (lane >> 4) * 8;
    const int rb = lr + (lane >> 4) * 8;         // B-fragment rows
    const int cb = ((lane >> 3) & 1) * 8;

    const uint32_t smem_u = (uint32_t)__cvta_generic_to_shared(smemh);
    const int n_iters = K >> 6;

    auto issue = [&](int it) {
        int k0 = it << 6;
        __half* st = smemh + (it % 3) * GSTAGE;
        #pragma unroll
        for (int j = 0; j < 16; j++) {
            int idx = j * 128 + tid;       // 0..2047
            int row = idx >> 3;
            int seg = (idx & 7) * 8;
            const __half* src = (row < BM)
                ? A + (size_t)(m0 + row) * K + k0 + seg
                : B + (size_t)(n0 + row - BM) * K + k0 + seg;
            cp_async16(st + row * HST + seg, src);
        }
    };

    issue(0); cp_commit();
    issue(1); cp_commit();

    for (int i = 0; i < n_iters; i++) {
        cp_wait<1>();
        __syncthreads();
        if (i + 2 < n_iters) issue(i + 2);
        cp_commit();

        const uint32_t base = smem_u + (uint32_t)((i % 3) * GSTAGE * 2);

        #pragma unroll
        for (int ka = 0; ka < 4; ka++) {
            const int kb = ka * 16;
            uint32_t af[4][4], bf[8][2];
            #pragma unroll
            for (int ma = 0; ma < 4; ma++)
                ldmx4(af[ma][0], af[ma][1], af[ma][2], af[ma][3],
                      base + 2u * (uint32_t)((wm * 64 + ma * 16 + ra) * HST + kb + ca));
            #pragma unroll
            for (int np = 0; np < 4; np++)
                ldmx4(bf[2*np][0], bf[2*np][1], bf[2*np+1][0], bf[2*np+1][1],
                      base + 2u * (uint32_t)((BM + wn * 64 + np * 16 + rb) * HST + kb + cb));
            #pragma unroll
            for (int ma = 0; ma < 4; ma++)
                #pragma unroll
                for (int na = 0; na < 8; na++)
                    mma_f16(acc[ma][na], af[ma], bf[na]);
        }
    }
    cp_wait<0>();
    __syncthreads();
}

// ---------------------------------------------------------------------------
// Kernel 1: QKV GEMM + register RoPE + fp16 scatter.
// Warp col block == one head (64 cols); head = 2*bx + wn.
// RoPE partner c^32 is na^4, SAME thread. grid = (24, 32).
// ---------------------------------------------------------------------------
__global__ __launch_bounds__(128)
void qkv_rope_kernel() {
    extern __shared__ char dsm_c[];
    __half* smh = (__half*)dsm_c;

    const int tid = threadIdx.x;
    const int m0 = blockIdx.y * BM;
    const int n0 = blockIdx.x * BN;
    const int warp = tid >> 5;
    const int lane = tid & 31;
    const int wm = warp >> 1, wn = warp & 1;
    const int grp = lane >> 2, tg = lane & 3;

    float acc[4][8][4];
    #pragma unroll
    for (int i = 0; i < 4; i++)
        #pragma unroll
        for (int j = 0; j < 8; j++)
            #pragma unroll
            for (int v = 0; v < 4; v++) acc[i][j][v] = 0.0f;

    gemm_core_f16(g_xh, g_wqh, m0, n0, 1024, smh, acc);

    const int basehead = (n0 >> 6) + wn;      // 0..47, uniform per warp

    if (basehead < 32) {
        // ---- stage cos/sin for this tile's 128 rows (32 angles each)
        float* sCos = (float*)dsm_c;
        float* sSin = sCos + BM * 32;
        for (int i = tid; i < BM * 32; i += 128) {
            int r = i >> 5, c = i & 31;
            int s = (m0 + r) & 2047;
            sCos[i] = g_cos[(s << 5) + c];
            sSin[i] = g_sin[(s << 5) + c];
        }
        __syncthreads();

        const float qs = (basehead < 16) ? QSCALE : 1.0f;
        #pragma unroll
        for (int ma = 0; ma < 4; ma++) {
            #pragma unroll
            for (int hf = 0; hf < 2; hf++) {
                int r = wm * 64 + ma * 16 + grp + hf * 8;
                int t = m0 + r;
                int b = t >> 11, s = t & 2047;
                __half* dst = (basehead < 16)
                    ? g_qh + (((size_t)(b * Hh + basehead)      << 11) + s) * 64
                    : g_kh + (((size_t)(b * Hh + basehead - 16) << 11) + s) * 64;
                #pragma unroll
                for (int na = 0; na < 8; na++) {
                    int c0 = na * 8 + 2 * tg;
                    float v0 = acc[ma][na][hf*2 + 0];
                    float v1 = acc[ma][na][hf*2 + 1];
                    float p0 = acc[ma][na ^ 4][hf*2 + 0];
                    float p1 = acc[ma][na ^ 4][hf*2 + 1];
                    float sg = (na < 4) ? -1.0f : 1.0f;
                    float cs0 = sCos[(r << 5) + (c0 & 31)];
                    float sn0 = sSin[(r << 5) + (c0 & 31)];
                    float cs1 = sCos[(r << 5) + ((c0 + 1) & 31)];
                    float sn1 = sSin[(r << 5) + ((c0 + 1) & 31)];
                    float o0 = (v0 * cs0 + sg * p0 * sn0) * qs;
                    float o1 = (v1 * cs1 + sg * p1 * sn1) * qs;
                    *(uint32_t*)(dst + c0) = pack_half2(o0, o1);
                }
            }
        }
    } else {
        #pragma unroll
        for (int ma = 0; ma < 4; ma++) {
            #pragma unroll
            for (int hf = 0; hf < 2; hf++) {
                int r = wm * 64 + ma * 16 + grp + hf * 8;
                int t = m0 + r;
                int b = t >> 11, s = t & 2047;
                __half* dst = g_vh +
                    (((size_t)(b * Hh + basehead - 32) << 11) + s) * 64;
                #pragma unroll
                for (int na = 0; na < 8; na++) {
                    int c0 = na * 8 + 2 * tg;
                    *(uint32_t*)(dst + c0) =
                        pack_half2(acc[ma][na][hf*2], acc[ma][na][hf*2 + 1]);
                }
            }
        }
    }
}

// ---------------------------------------------------------------------------
// Kernel 3: output projection + bias (128x128 tile). grid = (8, 32).
// ---------------------------------------------------------------------------
__global__ __launch_bounds__(128)
void proj_kernel(const float* __restrict__ bias, float* __restrict__ out) {
    extern __shared__ char dsm_c[];
    __half* smh = (__half*)dsm_c;

    const int tid = threadIdx.x;
    const int m0 = blockIdx.y * BM;
    const int n0 = blockIdx.x * BN;
    const int warp = tid >> 5;
    const int lane = tid & 31;
    const int wm = warp >> 1, wn = warp & 1;
    const int grp = lane >> 2, tg = lane & 3;

    float acc[4][8][4];
    #pragma unroll
    for (int i = 0; i < 4; i++)
        #pragma unroll
        for (int j = 0; j < 8; j++)
            #pragma unroll
            for (int v = 0; v < 4; v++) acc[i][j][v] = 0.0f;

    gemm_core_f16(g_oh, g_woh, m0, n0, 1024, smh, acc);

    #pragma unroll
    for (int ma = 0; ma < 4; ma++) {
        int r0 = m0 + wm * 64 + ma * 16 + grp;
        #pragma unroll
        for (int na = 0; na < 8; na++) {
            int col = n0 + wn * 64 + na * 8 + 2 * tg;
            float b0 = bias[col], b1 = bias[col + 1];
            *(float2*)(out + (size_t)r0 * 1024 + col) =
                make_float2(acc[ma][na][0] + b0, acc[ma][na][1] + b1);
            *(float2*)(out + (size_t)(r0 + 8) * 1024 + col) =
                make_float2(acc[ma][na][2] + b0, acc[ma][na][3] + b1);
        }
    }
}

// ---------------------------------------------------------------------------
// Kernel 2: causal flash attention (R12 version — at its HMMA floor).
// fp16 mma, register P, fixed-shift exp2 softmax, ones-column l,
// 3-stage cp.async K/V ring, LPT grid.
// ---------------------------------------------------------------------------
#define ATTN_SMEM ((128 * HST + 6 * 64 * HST) * 2)   // 73728 B

__global__ __launch_bounds__(256)
void attn_kernel() {
    extern __shared__ char asc[];
    __half* sQ  = (__half*)asc;
    __half* sKs = sQ + 128 * HST;
    __half* sVs = sKs + 3 * 64 * HST;

    const int tid  = threadIdx.x;
    const int warp = tid >> 5;
    const int lane = tid & 31;
    const int grp  = lane >> 2;
    const int tg   = lane & 3;

    const int lr8 = lane & 7;
    const int ra = lr8 + ((lane >> 3) & 1) * 8;
    const int ca = (lane >> 4) * 8;
    const int rb = lr8 + (lane >> 4) * 8;
    const int cb = ((lane >> 3) & 1) * 8;

    const int bh = blockIdx.x;                            // fast axis: heads
    const int q0 = (gridDim.y - 1 - blockIdx.y) * 128;    // heavy q first
    const int b  = bh >> 4;
    const int h  = bh & 15;

    const __half* Qg = g_qh + ((size_t)bh * Ss + q0) * 64;
    const __half* Kg = g_kh + (size_t)bh * Ss * 64;
    const __half* Vg = g_vh + (size_t)bh * Ss * 64;

    const uint32_t sQ_u  = (uint32_t)__cvta_generic_to_shared(sQ);
    const uint32_t sKs_u = (uint32_t)__cvta_generic_to_shared(sKs);
    const uint32_t sVs_u = (uint32_t)__cvta_generic_to_shared(sVs);

    const int n_tiles = (q0 >> 6) + 2;

    auto kv_issue = [&](int tile) {
        int kv = tile << 6;
        int st = tile % 3;
        __half* dK = sKs + st * 64 * HST;
        __half* dV = sVs + st * 64 * HST;
        const int r = tid >> 2;
        const int s2 = (tid & 3) * 16;
        #pragma unroll
        for (int i = 0; i < 2; i++) {
            cp_async16(dK + r * HST + s2 + i * 8,
                       Kg + (size_t)(kv + r) * 64 + s2 + i * 8);
            cp_async16(dV + r * HST + s2 + i * 8,
                       Vg + (size_t)(kv + r) * 64 + s2 + i * 8);
        }
    };

    // V pad columns: col 64 = 1.0 (l-column), 65..71 = 0. Written once.
    if (tid < 192) {
        int st = tid / 64;
        int r  = tid % 64;
        __half* pad = sVs + st * 64 * HST + r * HST + 64;
        *(uint4*)pad = make_uint4(0x00003C00u, 0u, 0u, 0u);
    }

    {
        const int r = tid >> 1;
        const int s4 = (tid & 1) * 32;
        #pragma unroll
        for (int i = 0; i < 4; i++)
            cp_async16(sQ + r * HST + s4 + i * 8,
                       Qg + (size_t)r * 64 + s4 + i * 8);
    }
    cp_commit();
    kv_issue(0); cp_commit();
    kv_issue(1); cp_commit();

    cp_wait<2>();
    __syncthreads();

    uint32_t qa[4][4];
    #pragma unroll
    for (int ka = 0; ka < 4; ka++)
        ldmx4(qa[ka][0], qa[ka][1], qa[ka][2], qa[ka][3],
              sQ_u + 2u * (uint32_t)((warp * 16 + ra) * HST + ka * 16 + ca));

    float oacc[8][4];
    #pragma unroll
    for (int na = 0; na < 8; na++)
        #pragma unroll
        for (int v = 0; v < 4; v++) oacc[na][v] = 0.0f;
    float oaccL[4] = {0.0f, 0.0f, 0.0f, 0.0f};

    const int row0g = q0 + warp * 16 + grp;
    const int row1g = row0g + 8;

    for (int ti = 0; ti < n_tiles; ti++) {
        cp_wait<1>();
        __syncthreads();
        if (ti + 2 < n_tiles) kv_issue(ti + 2);
        cp_commit();

        const int st = ti % 3;
        const uint32_t cK_u = sKs_u + (uint32_t)(st * 64 * HST * 2);
        const uint32_t cV_u = sVs_u + (uint32_t)(st * 64 * HST * 2);
        const int kv0 = ti << 6;

        float sacc[8][4];
        #pragma unroll
        for (int na = 0; na < 8; na++)
            #pragma unroll
            for (int v = 0; v < 4; v++) sacc[na][v] = -MSHIFT;

        #pragma unroll
        for (int ka = 0; ka < 4; ka++) {
            const int kb = ka * 16;
            uint32_t bf[8][2];
            #pragma unroll
            for (int np = 0; np < 4; np++)
                ldmx4(bf[2*np][0], bf[2*np][1], bf[2*np+1][0], bf[2*np+1][1],
                      cK_u + 2u * (uint32_t)((np * 16 + rb) * HST + kb + cb));
            #pragma unroll
            for (int na = 0; na < 8; na++)
                mma_f16(sacc[na], qa[ka], bf[na]);
        }

        if (kv0 + 64 > q0) {
            #pragma unroll
            for (int na = 0; na < 8; na++) {
                int c0 = kv0 + na * 8 + 2 * tg;
                if (c0     > row0g) sacc[na][0] = -1e30f;
                if (c0 + 1 > row0g) sacc[na][1] = -1e30f;
                if (c0     > row1g) sacc[na][2] = -1e30f;
                if (c0 + 1 > row1g) sacc[na][3] = -1e30f;
            }
        }

        uint32_t pf[8][2];
        #pragma unroll
        for (int na = 0; na < 8; na++) {
            pf[na][0] = pack_half2(ex2f(sacc[na][0]), ex2f(sacc[na][1]));
            pf[na][1] = pack_half2(ex2f(sacc[na][2]), ex2f(sacc[na][3]));
        }

        #pragma unroll
        for (int ka2 = 0; ka2 < 4; ka2++) {
            uint32_t pa[4] = { pf[2*ka2][0],   pf[2*ka2][1],
                               pf[2*ka2+1][0], pf[2*ka2+1][1] };
            #pragma unroll
            for (int np = 0; np < 4; np++) {
                uint32_t b0, b1, b2, b3;
                ldmx4t(b0, b1, b2, b3,
                       cV_u + 2u * (uint32_t)((ka2 * 16 + ra) * HST + np * 16 + ca));
                uint32_t bf0[2] = {b0, b1};
                uint32_t bf1[2] = {b2, b3};
                mma_f16(oacc[2*np],     pa, bf0);
                mma_f16(oacc[2*np + 1], pa, bf1);
            }
            uint32_t lb0, lb1;
            ldmx2t(lb0, lb1,
                   cV_u + 2u * (uint32_t)((ka2 * 16 + ra) * HST + 64));
            uint32_t lbf[2] = {lb0, lb1};
            mma_f16(oaccL, pa, lbf);
        }
    }

    {
        int src = lane & ~3;
        float l0 = __shfl_sync(0xffffffffu, oaccL[0], src);
        float l1 = __shfl_sync(0xffffffffu, oaccL[2], src);
        float inv0 = 1.0f / l0;
        float inv1 = 1.0f / l1;
        __half* O0 = g_oh + ((size_t)(b * Ss) + row0g) * 1024 + h * 64;
        __half* O1 = g_oh + ((size_t)(b * Ss) + row1g) * 1024 + h * 64;
        #pragma unroll
        for (int na = 0; na < 8; na++) {
            int c0 = na * 8 + 2 * tg;
            *(uint32_t*)(O0 + c0) = pack_half2(oacc[na][0] * inv0,
                                               oacc[na][1] * inv0);
            *(uint32_t*)(O1 + c0) = pack_half2(oacc[na][2] * inv1,
                                               oacc[na][3] * inv1);
        }
    }
}

// ---------------------------------------------------------------------------
extern "C" void kernel_launch(void* const* d_in, const int* in_sizes, int n_in,
                              void* d_out, int out_size) {
    const float* x     = (const float*)d_in[0];
    const float* w_qkv = (const float*)d_in[1];
    const float* w_out = (const float*)d_in[2];
    const float* b_out = (const float*)d_in[3];
    float* out = (float*)d_out;

    rope_table_kernel<<<(Ss * 32 + 255) / 256, 256>>>();

    f2h_all_kernel<<<((N_X + N_WQ + N_WO) / 8 + 255) / 256, 256>>>(x, w_qkv, w_out);

    cudaFuncSetAttribute(qkv_rope_kernel,
                         cudaFuncAttributeMaxDynamicSharedMemorySize, GEMM_SMEM);
    cudaFuncSetAttribute(proj_kernel,
                         cudaFuncAttributeMaxDynamicSharedMemorySize, GEMM_SMEM);
    cudaFuncSetAttribute(attn_kernel,
                         cudaFuncAttributeMaxDynamicSharedMemorySize, ATTN_SMEM);

    qkv_rope_kernel<<<dim3(E3 / BN, Tt / BM), 128, GEMM_SMEM>>>();

    attn_kernel<<<dim3(Bb * Hh, Ss / 128), 256, ATTN_SMEM>>>();

    proj_kernel<<<dim3(Dd / BN, Tt / BM), 128, GEMM_SMEM>>>(b_out, out);
}